// round 2
// baseline (speedup 1.0000x reference)
#include <cuda_runtime.h>
#include <cstdint>

#define Bn 16
#define Cn 64
#define Hn 160
#define Wn 160
#define HP 161
#define TJ 64
#define JT 3
#define IT 81              // ceil(162/2) row-pairs (row 161 is auto-predicated no-op)
#define CONV_BLOCKS (Bn * IT * JT)
#define WT_STRIDE 66
#define LU_STRIDE 65
#define SMEM_BYTES (64 * WT_STRIDE * 4 + 2 * 64 * 64 * 4)   // 49664

__device__ __forceinline__ float2 ffma2(float2 a, float2 b, float2 c) {
    unsigned long long A = *reinterpret_cast<unsigned long long*>(&a);
    unsigned long long Bv = *reinterpret_cast<unsigned long long*>(&b);
    unsigned long long Cv = *reinterpret_cast<unsigned long long*>(&c);
    unsigned long long D;
    asm("fma.rn.f32x2 %0, %1, %2, %3;" : "=l"(D) : "l"(A), "l"(Bv), "l"(Cv));
    return *reinterpret_cast<float2*>(&D);
}

// ---- block 0: all 9 logdet LUs (fp64, partial pivot) + finalize ----
__device__ void logdet_all(const float* __restrict__ wgt,
                           const float* __restrict__ ldin,
                           float* __restrict__ outld,
                           unsigned char* smem_raw)
{
    double* A = reinterpret_cast<double*>(smem_raw);   // [n][LU_STRIDE]
    __shared__ double s_val[2];
    __shared__ int    s_idx[2];
    __shared__ int    s_piv;
    __shared__ double s_acc;
    __shared__ double s_tot;

    const int tid = threadIdx.x;
    if (tid == 0) s_tot = 0.0;

    for (int r = 0; r < 9; r++) {
        const int n = (r == 0) ? 64 : (r <= 4 ? 32 : 16);
        const double pixw = (r == 0) ? (double)(Hn - 1) * (double)(Wn - 1)
                                     : (r <= 4 ? (double)(Wn - 1) : 1.0);
        // channel maps: t:{2,3} b:{0,1} l:{1,3} r:{0,2}; tl=3,tr=2,bl=1,br=0
        auto chan = [&](int m) -> int {
            if (r == 0) return m;
            if (r <= 4) {
                const int t2[4][2] = {{2, 3}, {0, 1}, {1, 3}, {0, 2}};
                return 4 * (m >> 1) + t2[r - 1][m & 1];
            }
            const int t1[4] = {3, 2, 1, 0};
            return 4 * m + t1[r - 5];
        };

        __syncthreads();
        for (int idx = tid; idx < n * n; idx += 256) {
            int ri = idx / n, ci = idx % n;
            A[ri * LU_STRIDE + ci] = (double)wgt[chan(ri) * Cn + chan(ci)];
        }
        if (tid == 0) s_acc = 0.0;
        __syncthreads();

        for (int k = 0; k < n; k++) {
            double v = -1.0;
            int vi = tid;
            if (tid >= k && tid < n) v = fabs(A[tid * LU_STRIDE + k]);
            if (tid < 64) {
#pragma unroll
                for (int off = 16; off; off >>= 1) {
                    double ov = __shfl_down_sync(0xffffffffu, v, off);
                    int    oi = __shfl_down_sync(0xffffffffu, vi, off);
                    if (ov > v) { v = ov; vi = oi; }
                }
                if ((tid & 31) == 0) { s_val[tid >> 5] = v; s_idx[tid >> 5] = vi; }
            }
            __syncthreads();
            if (tid == 0) {
                double bv = s_val[0]; int bi = s_idx[0];
                if (n > 32 && s_val[1] > bv) { bv = s_val[1]; bi = s_idx[1]; }
                s_piv = bi;
                s_acc += log(bv);
            }
            __syncthreads();
            const int piv = s_piv;
            if (piv != k && tid < n) {
                double t = A[k * LU_STRIDE + tid];
                A[k * LU_STRIDE + tid]   = A[piv * LU_STRIDE + tid];
                A[piv * LU_STRIDE + tid] = t;
            }
            __syncthreads();
            if (tid > k && tid < n) {
                double m = A[tid * LU_STRIDE + k] / A[k * LU_STRIDE + k];
                for (int c = k + 1; c < n; c++)
                    A[tid * LU_STRIDE + c] -= m * A[k * LU_STRIDE + c];
            }
            __syncthreads();
        }
        if (tid == 0) s_tot += s_acc * pixw;
    }
    __syncthreads();
    if (tid < Bn) outld[tid] = ldin[tid] + (float)s_tot;
}

// ---- merged kernel: block 0 = logdet; blocks 1.. = conv (2 rows/block) ----
extern "C" __global__ void __launch_bounds__(256, 4)
ic1x1_kernel(const float* __restrict__ x, const float* __restrict__ wgt,
             const float* __restrict__ ldin,
             float* __restrict__ out, float* __restrict__ outld)
{
    extern __shared__ __align__(16) unsigned char smem_raw[];

    const int bx = blockIdx.x;
    if (bx == 0) { logdet_all(wgt, ldin, outld, smem_raw); return; }

    const int id = bx - 1;
    const int jt = id % JT;
    const int it = (id / JT) % IT;
    const int b  = id / (JT * IT);
    const int j0 = jt * TJ;

    float* wt  = reinterpret_cast<float*>(smem_raw);   // wt[k][co], stride 66
    float* zsh = wt + 64 * WT_STRIDE;                  // [2][64][64]

    const int tid  = threadIdx.x;
    const int team = tid >> 7;        // 0/1 -> row i0+team
    const int ttid = tid & 127;
    const int i    = 2 * it + team;   // 0..161 (161 auto-predicated everywhere)

    // cooperative W load + transpose (all 256 threads)
#pragma unroll
    for (int n = 0; n < 16; n++) {
        int idx = tid + n * 256;
        int co = idx >> 6;
        int k  = idx & 63;
        wt[k * WT_STRIDE + co] = wgt[idx];
    }
    // gather shifted-grid tile for this team's row
    float* zt = zsh + team * 64 * 64;
#pragma unroll
    for (int n = 0; n < 32; n++) {
        int idx = ttid + n * 128;
        int k  = idx >> 6;   // c_in
        int jj = idx & 63;
        int p = (k >> 1) & 1, q = k & 1;
        int pp = 1 - p, qq = 1 - q;
        int sc = (k & ~3) | (pp << 1) | qq;
        int si = i - pp;
        int sj = j0 + jj - qq;
        float v = 0.0f;
        if ((unsigned)si < (unsigned)Hn && (unsigned)sj < (unsigned)Wn)
            v = x[((b * Cn + sc) * Hn + si) * Wn + sj];
        zt[k * 64 + jj] = v;
    }
    __syncthreads();

    const int tr = ttid >> 4;   // c_out group of 8
    const int tc = ttid & 15;   // j lane (4 j, stride 16)

    float2 acc[4][4];
#pragma unroll
    for (int u = 0; u < 4; u++)
#pragma unroll
        for (int rr = 0; rr < 4; rr++) acc[u][rr] = make_float2(0.0f, 0.0f);

    const float* wrow = wt + tr * 8;
    const float* zcol = zt + tc;

#pragma unroll 4
    for (int k = 0; k < 64; k++) {
        float2 w0 = *reinterpret_cast<const float2*>(wrow + k * WT_STRIDE + 0);
        float2 w1 = *reinterpret_cast<const float2*>(wrow + k * WT_STRIDE + 2);
        float2 w2 = *reinterpret_cast<const float2*>(wrow + k * WT_STRIDE + 4);
        float2 w3 = *reinterpret_cast<const float2*>(wrow + k * WT_STRIDE + 6);
#pragma unroll
        for (int rr = 0; rr < 4; rr++) {
            float zv = zcol[k * 64 + 16 * rr];
            float2 zz = make_float2(zv, zv);
            acc[0][rr] = ffma2(w0, zz, acc[0][rr]);
            acc[1][rr] = ffma2(w1, zz, acc[1][rr]);
            acc[2][rr] = ffma2(w2, zz, acc[2][rr]);
            acc[3][rr] = ffma2(w3, zz, acc[3][rr]);
        }
    }

    // scatter through inverse shift (predication == region masks)
#pragma unroll
    for (int u = 0; u < 4; u++) {
#pragma unroll
        for (int h = 0; h < 2; h++) {
            int co = tr * 8 + 2 * u + h;
            int P = (co >> 1) & 1, Q = co & 1;
            int dc = (co & ~3) | ((1 - P) << 1) | (1 - Q);
            int di = i - (1 - P);
            if ((unsigned)di >= (unsigned)Hn) continue;
            float* orow = out + ((b * Cn + dc) * Hn + di) * Wn;
#pragma unroll
            for (int rr = 0; rr < 4; rr++) {
                int j  = j0 + tc + 16 * rr;
                int dj = j - (1 - Q);
                if ((unsigned)dj < (unsigned)Wn)
                    orow[dj] = h ? acc[u][rr].y : acc[u][rr].x;
            }
        }
    }
}

extern "C" void kernel_launch(void* const* d_in, const int* in_sizes, int n_in,
                              void* d_out, int out_size)
{
    const float *x = nullptr, *ld = nullptr, *w = nullptr;
    for (int k = 0; k < n_in; k++) {
        if (in_sizes[k] == Cn * Cn)      w  = (const float*)d_in[k];
        else if (in_sizes[k] == Bn)      ld = (const float*)d_in[k];
        else                             x  = (const float*)d_in[k];
    }
    float* out   = (float*)d_out;
    float* outld = out + (out_size - Bn);

    cudaFuncSetAttribute(ic1x1_kernel,
                         cudaFuncAttributeMaxDynamicSharedMemorySize, SMEM_BYTES);
    ic1x1_kernel<<<1 + CONV_BLOCKS, 256, SMEM_BYTES>>>(x, w, ld, out, outld);
}

// round 3
// speedup vs baseline: 2.5657x; 2.5657x over previous
#include <cuda_runtime.h>
#include <cstdint>

#define Bn 16
#define Cn 64
#define Hn 160
#define Wn 160
#define HP 161
#define TJ 64
#define JT 3
#define NLOG 9
#define CONV_BLOCKS (Bn * HP * JT)
#define WT_STRIDE 68            // 68*4 = 272 = 16*17 -> float4-aligned rows
#define LU_STRIDE 65
// smem: wt 64*68*4 = 17408  +  z 64*64*4 = 16384  -> 33792 ; LU needs 64*65*8 = 33280 (fits)
#define SMEM_BYTES 33792

__device__ double g_dlog[NLOG];
__device__ int    g_count = 0;

__device__ __forceinline__ float2 ffma2(float2 a, float2 b, float2 c) {
    unsigned long long A = *reinterpret_cast<unsigned long long*>(&a);
    unsigned long long Bv = *reinterpret_cast<unsigned long long*>(&b);
    unsigned long long Cv = *reinterpret_cast<unsigned long long*>(&c);
    unsigned long long D;
    asm("fma.rn.f32x2 %0, %1, %2, %3;" : "=l"(D) : "l"(A), "l"(Bv), "l"(Cv));
    return *reinterpret_cast<float2*>(&D);
}

// ---- blocks 0..8: one fp64 LU each; 9th finisher sums (fixed order) + writes logdet ----
__device__ void logdet_block(int r, const float* __restrict__ wgt,
                             const float* __restrict__ ldin,
                             float* __restrict__ outld,
                             unsigned char* smem_raw)
{
    double* A = reinterpret_cast<double*>(smem_raw);   // [n][LU_STRIDE]
    __shared__ double s_val[2];
    __shared__ int    s_idx[2];
    __shared__ int    s_piv;
    __shared__ double s_acc;
    __shared__ int    s_ticket;

    const int tid = threadIdx.x;
    const int n   = (r == 0) ? 64 : (r <= 4 ? 32 : 16);
    const double pixw = (r == 0) ? (double)(Hn - 1) * (double)(Wn - 1)
                                 : (r <= 4 ? (double)(Wn - 1) : 1.0);
    // channel maps: t:{2,3} b:{0,1} l:{1,3} r:{0,2}; tl=3,tr=2,bl=1,br=0
    auto chan = [&](int m) -> int {
        if (r == 0) return m;
        if (r <= 4) {
            const int t2[4][2] = {{2, 3}, {0, 1}, {1, 3}, {0, 2}};
            return 4 * (m >> 1) + t2[r - 1][m & 1];
        }
        const int t1[4] = {3, 2, 1, 0};
        return 4 * m + t1[r - 5];
    };

    for (int idx = tid; idx < n * n; idx += 256) {
        int ri = idx / n, ci = idx % n;
        A[ri * LU_STRIDE + ci] = (double)wgt[chan(ri) * Cn + chan(ci)];
    }
    if (tid == 0) s_acc = 0.0;
    __syncthreads();

    for (int k = 0; k < n; k++) {
        double v = -1.0;
        int vi = tid;
        if (tid >= k && tid < n) v = fabs(A[tid * LU_STRIDE + k]);
        if (tid < 64) {
#pragma unroll
            for (int off = 16; off; off >>= 1) {
                double ov = __shfl_down_sync(0xffffffffu, v, off);
                int    oi = __shfl_down_sync(0xffffffffu, vi, off);
                if (ov > v) { v = ov; vi = oi; }
            }
            if ((tid & 31) == 0) { s_val[tid >> 5] = v; s_idx[tid >> 5] = vi; }
        }
        __syncthreads();
        if (tid == 0) {
            double bv = s_val[0]; int bi = s_idx[0];
            if (n > 32 && s_val[1] > bv) { bv = s_val[1]; bi = s_idx[1]; }
            s_piv = bi;
            s_acc += log(bv);   // log|pivot|
        }
        __syncthreads();
        const int piv = s_piv;
        if (piv != k && tid < n) {
            double t = A[k * LU_STRIDE + tid];
            A[k * LU_STRIDE + tid]   = A[piv * LU_STRIDE + tid];
            A[piv * LU_STRIDE + tid] = t;
        }
        __syncthreads();
        if (tid > k && tid < n) {
            double m = A[tid * LU_STRIDE + k] / A[k * LU_STRIDE + k];
            for (int c = k + 1; c < n; c++)
                A[tid * LU_STRIDE + c] -= m * A[k * LU_STRIDE + c];
        }
        __syncthreads();
    }

    if (tid == 0) {
        g_dlog[r] = s_acc * pixw;
        __threadfence();
        s_ticket = atomicAdd(&g_count, 1);
    }
    __syncthreads();
    if (s_ticket == NLOG - 1) {     // last finisher: deterministic fixed-order sum
        __threadfence();
        if (tid < Bn) {
            volatile double* gd = g_dlog;
            double s = 0.0;
#pragma unroll
            for (int k = 0; k < NLOG; k++) s += gd[k];
            outld[tid] = ldin[tid] + (float)s;
        }
        if (tid == 0) g_count = 0;  // reset for next graph replay
    }
}

// ---- single merged kernel ----
extern "C" __global__ void __launch_bounds__(256)
ic1x1_kernel(const float* __restrict__ x, const float* __restrict__ wgt,
             const float* __restrict__ ldin,
             float* __restrict__ out, float* __restrict__ outld)
{
    __shared__ __align__(16) unsigned char smem_raw[SMEM_BYTES];

    const int bx = blockIdx.x;
    if (bx < NLOG) { logdet_block(bx, wgt, ldin, outld, smem_raw); return; }

    const int id = bx - NLOG;
    const int jt = id % JT;
    const int i  = (id / JT) % HP;   // 0..160 (shifted-grid row)
    const int b  = id / (JT * HP);
    const int j0 = jt * TJ;

    float* wt = reinterpret_cast<float*>(smem_raw);   // transposed W: wt[k*68 + co]
    float* zt = wt + 64 * WT_STRIDE;                  // z tile: zt[k*64 + jj]

    const int tid = threadIdx.x;

    // W load (coalesced) + transpose into smem
#pragma unroll
    for (int n = 0; n < 16; n++) {
        int idx = tid + n * 256;
        int co = idx >> 6;
        int k  = idx & 63;
        wt[k * WT_STRIDE + co] = wgt[idx];
    }
    // gather shifted-grid tile (uniform boundary rule == region masks)
#pragma unroll
    for (int n = 0; n < 16; n++) {
        int idx = tid + n * 256;
        int k  = idx >> 6;   // c_in
        int jj = idx & 63;
        int p = (k >> 1) & 1, q = k & 1;
        int pp = 1 - p, qq = 1 - q;
        int sc = (k & ~3) | (pp << 1) | qq;   // flipped source channel
        int si = i - pp;
        int sj = j0 + jj - qq;
        float v = 0.0f;
        if ((unsigned)si < (unsigned)Hn && (unsigned)sj < (unsigned)Wn)
            v = x[((b * Cn + sc) * Hn + si) * Wn + sj];
        zt[k * 64 + jj] = v;
    }
    __syncthreads();

    const int cg = tid >> 4;    // 0..15 : c_out group of 4
    const int tc = tid & 15;    // 0..15 : j group of 4 (contiguous)

    float2 acc[2][4];           // [co-pair][j]
#pragma unroll
    for (int p = 0; p < 2; p++)
#pragma unroll
        for (int u = 0; u < 4; u++) acc[p][u] = make_float2(0.0f, 0.0f);

    const float* wbase = wt + cg * 4;
    const float* zbase = zt + tc * 4;

#pragma unroll 4
    for (int k = 0; k < 64; k++) {
        float4 wv = *reinterpret_cast<const float4*>(wbase + k * WT_STRIDE);
        float4 zv = *reinterpret_cast<const float4*>(zbase + k * 64);
        float2 w01 = make_float2(wv.x, wv.y);
        float2 w23 = make_float2(wv.z, wv.w);
        float2 z0 = make_float2(zv.x, zv.x);
        float2 z1 = make_float2(zv.y, zv.y);
        float2 z2 = make_float2(zv.z, zv.z);
        float2 z3 = make_float2(zv.w, zv.w);
        acc[0][0] = ffma2(w01, z0, acc[0][0]);
        acc[1][0] = ffma2(w23, z0, acc[1][0]);
        acc[0][1] = ffma2(w01, z1, acc[0][1]);
        acc[1][1] = ffma2(w23, z1, acc[1][1]);
        acc[0][2] = ffma2(w01, z2, acc[0][2]);
        acc[1][2] = ffma2(w23, z2, acc[1][2]);
        acc[0][3] = ffma2(w01, z3, acc[0][3]);
        acc[1][3] = ffma2(w23, z3, acc[1][3]);
    }

    // scatter through inverse shift (predication == region masks)
#pragma unroll
    for (int p = 0; p < 2; p++) {
#pragma unroll
        for (int h = 0; h < 2; h++) {
            int co = cg * 4 + 2 * p + h;
            int P = (co >> 1) & 1, Q = co & 1;
            int dc = (co & ~3) | ((1 - P) << 1) | (1 - Q);
            int di = i - (1 - P);
            if ((unsigned)di >= (unsigned)Hn) continue;
            float* orow = out + ((b * Cn + dc) * Hn + di) * Wn;
#pragma unroll
            for (int u = 0; u < 4; u++) {
                int j  = j0 + tc * 4 + u;
                int dj = j - (1 - Q);
                if ((unsigned)dj < (unsigned)Wn)
                    orow[dj] = h ? acc[p][u].y : acc[p][u].x;
            }
        }
    }
}

extern "C" void kernel_launch(void* const* d_in, const int* in_sizes, int n_in,
                              void* d_out, int out_size)
{
    const float *x = nullptr, *ld = nullptr, *w = nullptr;
    for (int k = 0; k < n_in; k++) {
        if (in_sizes[k] == Cn * Cn)      w  = (const float*)d_in[k];
        else if (in_sizes[k] == Bn)      ld = (const float*)d_in[k];
        else                             x  = (const float*)d_in[k];
    }
    float* out   = (float*)d_out;
    float* outld = out + (out_size - Bn);

    ic1x1_kernel<<<NLOG + CONV_BLOCKS, 256>>>(x, w, ld, out, outld);
}

// round 4
// speedup vs baseline: 2.6537x; 1.0343x over previous
#include <cuda_runtime.h>
#include <cstdint>

#define Bn 16
#define Cn 64
#define Hn 160
#define Wn 160
#define HP 161
#define TJ 64
#define JT 3
#define NLOG 9
#define CONV_BLOCKS (Bn * HP * JT)
#define WT_STRIDE 68            // 68*4 = 272 = 17*16 -> float4-aligned rows
#define LU_STRIDE 65
#define SMEM_BYTES 33792        // wt 17408 + zt 16384 ; LU needs 33280 (fits)
#define NTHR 64

__device__ double g_dlog[NLOG];
__device__ int    g_count = 0;

__device__ __forceinline__ float2 ffma2(float2 a, float2 b, float2 c) {
    unsigned long long A = *reinterpret_cast<unsigned long long*>(&a);
    unsigned long long Bv = *reinterpret_cast<unsigned long long*>(&b);
    unsigned long long Cv = *reinterpret_cast<unsigned long long*>(&c);
    unsigned long long D;
    asm("fma.rn.f32x2 %0, %1, %2, %3;" : "=l"(D) : "l"(A), "l"(Bv), "l"(Cv));
    return *reinterpret_cast<float2*>(&D);
}

// ---- blocks 0..8: one fp64 LU each; last finisher writes logdet ----
__device__ void logdet_block(int r, const float* __restrict__ wgt,
                             const float* __restrict__ ldin,
                             float* __restrict__ outld,
                             unsigned char* smem_raw)
{
    double* A = reinterpret_cast<double*>(smem_raw);   // [n][LU_STRIDE]
    __shared__ double s_val[2];
    __shared__ int    s_idx[2];
    __shared__ int    s_piv;
    __shared__ double s_acc;
    __shared__ int    s_ticket;

    const int tid = threadIdx.x;
    const int n   = (r == 0) ? 64 : (r <= 4 ? 32 : 16);
    const double pixw = (r == 0) ? (double)(Hn - 1) * (double)(Wn - 1)
                                 : (r <= 4 ? (double)(Wn - 1) : 1.0);
    auto chan = [&](int m) -> int {
        if (r == 0) return m;
        if (r <= 4) {
            const int t2[4][2] = {{2, 3}, {0, 1}, {1, 3}, {0, 2}};
            return 4 * (m >> 1) + t2[r - 1][m & 1];
        }
        const int t1[4] = {3, 2, 1, 0};
        return 4 * m + t1[r - 5];
    };

    for (int idx = tid; idx < n * n; idx += NTHR) {
        int ri = idx / n, ci = idx % n;
        A[ri * LU_STRIDE + ci] = (double)wgt[chan(ri) * Cn + chan(ci)];
    }
    if (tid == 0) s_acc = 0.0;
    __syncthreads();

    for (int k = 0; k < n; k++) {
        double v = -1.0;
        int vi = tid;
        if (tid >= k && tid < n) v = fabs(A[tid * LU_STRIDE + k]);
        {
#pragma unroll
            for (int off = 16; off; off >>= 1) {
                double ov = __shfl_down_sync(0xffffffffu, v, off);
                int    oi = __shfl_down_sync(0xffffffffu, vi, off);
                if (ov > v) { v = ov; vi = oi; }
            }
            if ((tid & 31) == 0) { s_val[tid >> 5] = v; s_idx[tid >> 5] = vi; }
        }
        __syncthreads();
        if (tid == 0) {
            double bv = s_val[0]; int bi = s_idx[0];
            if (n > 32 && s_val[1] > bv) { bv = s_val[1]; bi = s_idx[1]; }
            s_piv = bi;
            s_acc += log(bv);
        }
        __syncthreads();
        const int piv = s_piv;
        if (piv != k && tid < n) {
            double t = A[k * LU_STRIDE + tid];
            A[k * LU_STRIDE + tid]   = A[piv * LU_STRIDE + tid];
            A[piv * LU_STRIDE + tid] = t;
        }
        __syncthreads();
        if (tid > k && tid < n) {
            double m = A[tid * LU_STRIDE + k] / A[k * LU_STRIDE + k];
            for (int c = k + 1; c < n; c++)
                A[tid * LU_STRIDE + c] -= m * A[k * LU_STRIDE + c];
        }
        __syncthreads();
    }

    if (tid == 0) {
        g_dlog[r] = s_acc * pixw;
        __threadfence();
        s_ticket = atomicAdd(&g_count, 1);
    }
    __syncthreads();
    if (s_ticket == NLOG - 1) {
        __threadfence();
        if (tid < Bn) {
            volatile double* gd = g_dlog;
            double s = 0.0;
#pragma unroll
            for (int k = 0; k < NLOG; k++) s += gd[k];
            outld[tid] = ldin[tid] + (float)s;
        }
        if (tid == 0) g_count = 0;
    }
}

// ---- merged kernel: blocks 0..8 logdet; rest conv, 64 threads, 8co x 8j per thread ----
extern "C" __global__ void __launch_bounds__(NTHR)
ic1x1_kernel(const float* __restrict__ x, const float* __restrict__ wgt,
             const float* __restrict__ ldin,
             float* __restrict__ out, float* __restrict__ outld)
{
    __shared__ __align__(16) unsigned char smem_raw[SMEM_BYTES];

    const int bx = blockIdx.x;
    if (bx < NLOG) { logdet_block(bx, wgt, ldin, outld, smem_raw); return; }

    const int id = bx - NLOG;
    const int jt = id % JT;
    const int i  = (id / JT) % HP;   // shifted-grid row 0..160
    const int b  = id / (JT * HP);
    const int j0 = jt * TJ;

    float* wt = reinterpret_cast<float*>(smem_raw);   // wt[k*68 + co]
    float* zt = wt + 64 * WT_STRIDE;                  // zt[k*64 + jj]

    const int tid = threadIdx.x;

    // W load (coalesced) + transpose into smem
#pragma unroll
    for (int n = 0; n < 64; n++) {
        int idx = tid + n * NTHR;   // idx>>6 == n, idx&63 == tid
        wt[tid * WT_STRIDE + n] = wgt[idx];   // wt[k=tid][co=n] = W[co=n][k=tid]... careful
    }
    // NOTE: wgt[idx] = wgt[n*64 + tid] requires idx = n*64+tid: idx = tid + n*64 ✓
    // so co = n, k = tid  ->  wt[k*WT_STRIDE + co] = wt[tid*WT_STRIDE + n] ✓ (coalesced LDG)

    // gather shifted-grid tile (uniform boundary rule == region masks)
#pragma unroll
    for (int n = 0; n < 64; n++) {
        int k  = n;        // c_in row
        int jj = tid;      // lane = j (coalesced)
        int p = (k >> 1) & 1, q = k & 1;
        int pp = 1 - p, qq = 1 - q;
        int sc = (k & ~3) | (pp << 1) | qq;
        int si = i - pp;
        int sj = j0 + jj - qq;
        float v = 0.0f;
        if ((unsigned)si < (unsigned)Hn && (unsigned)sj < (unsigned)Wn)
            v = x[((b * Cn + sc) * Hn + si) * Wn + sj];
        zt[k * 64 + jj] = v;
    }
    __syncthreads();

    const int cg = tid & 7;    // c_out group of 8
    const int jg = tid >> 3;   // j group of 8

    float2 acc[4][8];          // [co-pair][j]
#pragma unroll
    for (int p = 0; p < 4; p++)
#pragma unroll
        for (int u = 0; u < 8; u++) acc[p][u] = make_float2(0.0f, 0.0f);

    const float* wbase = wt + cg * 8;
    const float* zbase = zt + jg * 8;

#pragma unroll 2
    for (int k = 0; k < 64; k++) {
        float4 wa = *reinterpret_cast<const float4*>(wbase + k * WT_STRIDE);
        float4 wb = *reinterpret_cast<const float4*>(wbase + k * WT_STRIDE + 4);
        float4 za = *reinterpret_cast<const float4*>(zbase + k * 64);
        float4 zb = *reinterpret_cast<const float4*>(zbase + k * 64 + 4);
        float2 w01 = make_float2(wa.x, wa.y);
        float2 w23 = make_float2(wa.z, wa.w);
        float2 w45 = make_float2(wb.x, wb.y);
        float2 w67 = make_float2(wb.z, wb.w);
        float zj[8] = {za.x, za.y, za.z, za.w, zb.x, zb.y, zb.z, zb.w};
#pragma unroll
        for (int u = 0; u < 8; u++) {
            float2 zz = make_float2(zj[u], zj[u]);
            acc[0][u] = ffma2(w01, zz, acc[0][u]);
            acc[1][u] = ffma2(w23, zz, acc[1][u]);
            acc[2][u] = ffma2(w45, zz, acc[2][u]);
            acc[3][u] = ffma2(w67, zz, acc[3][u]);
        }
    }

    // scatter through inverse shift (predication == region masks)
#pragma unroll
    for (int p = 0; p < 4; p++) {
#pragma unroll
        for (int h = 0; h < 2; h++) {
            int co = cg * 8 + 2 * p + h;
            int P = (co >> 1) & 1, Q = co & 1;
            int dc = (co & ~3) | ((1 - P) << 1) | (1 - Q);
            int di = i - (1 - P);
            if ((unsigned)di >= (unsigned)Hn) continue;
            float* orow = out + ((b * Cn + dc) * Hn + di) * Wn;
#pragma unroll
            for (int u = 0; u < 8; u++) {
                int j  = j0 + jg * 8 + u;
                int dj = j - (1 - Q);
                if ((unsigned)dj < (unsigned)Wn)
                    orow[dj] = h ? acc[p][u].y : acc[p][u].x;
            }
        }
    }
}

extern "C" void kernel_launch(void* const* d_in, const int* in_sizes, int n_in,
                              void* d_out, int out_size)
{
    const float *x = nullptr, *ld = nullptr, *w = nullptr;
    for (int k = 0; k < n_in; k++) {
        if (in_sizes[k] == Cn * Cn)      w  = (const float*)d_in[k];
        else if (in_sizes[k] == Bn)      ld = (const float*)d_in[k];
        else                             x  = (const float*)d_in[k];
    }
    float* out   = (float*)d_out;
    float* outld = out + (out_size - Bn);

    ic1x1_kernel<<<NLOG + CONV_BLOCKS, NTHR>>>(x, w, ld, out, outld);
}

// round 6
// speedup vs baseline: 2.9040x; 1.0943x over previous
#include <cuda_runtime.h>
#include <cuda_bf16.h>
#include <cstdint>

#define Bn 16
#define Cn 64
#define Hn 160
#define Wn 160
#define HP 161
#define NLOG 9
#define JT 3
#define NT_TILES (Bn * HP * JT)     // 7728 tiles of 64 pixels (row-segments)
#define NCONV 740                   // persistent conv blocks (148 * 5)
#define NTHR 128
#define LU_STRIDE 65
#define AST 72                      // bf16 element stride for A/W smem rows
#define SMEM_BYTES (4 * 64 * AST * 2)   // 4 tiles (Wh,Wl,Ah,Al) * 9216B = 36864

__device__ double g_dlog[NLOG];
__device__ int    g_count = 0;

__device__ __forceinline__ void mma_bf16(float* d, const uint32_t* a, uint32_t b0, uint32_t b1) {
    asm volatile(
        "mma.sync.aligned.m16n8k16.row.col.f32.bf16.bf16.f32 "
        "{%0,%1,%2,%3}, {%4,%5,%6,%7}, {%8,%9}, {%0,%1,%2,%3};"
        : "+f"(d[0]), "+f"(d[1]), "+f"(d[2]), "+f"(d[3])
        : "r"(a[0]), "r"(a[1]), "r"(a[2]), "r"(a[3]), "r"(b0), "r"(b1));
}
__device__ __forceinline__ uint32_t pack_bf16x2(float hi, float lo) {
    uint32_t r;
    asm("cvt.rn.bf16x2.f32 %0, %1, %2;" : "=r"(r) : "f"(hi), "f"(lo));
    return r;
}

// ---- blocks 0..8: one fp64 LU each; last finisher writes logdet ----
__device__ void logdet_block(int r, const float* __restrict__ wgt,
                             const float* __restrict__ ldin,
                             float* __restrict__ outld,
                             unsigned char* smem_raw)
{
    double* A = reinterpret_cast<double*>(smem_raw);
    __shared__ double s_val[2];
    __shared__ int    s_idx[2];
    __shared__ int    s_piv;
    __shared__ double s_acc;
    __shared__ int    s_ticket;

    const int tid = threadIdx.x;
    const int n   = (r == 0) ? 64 : (r <= 4 ? 32 : 16);
    const double pixw = (r == 0) ? (double)(Hn - 1) * (double)(Wn - 1)
                                 : (r <= 4 ? (double)(Wn - 1) : 1.0);
    auto chan = [&](int m) -> int {
        if (r == 0) return m;
        if (r <= 4) {
            const int t2[4][2] = {{2, 3}, {0, 1}, {1, 3}, {0, 2}};
            return 4 * (m >> 1) + t2[r - 1][m & 1];
        }
        const int t1[4] = {3, 2, 1, 0};
        return 4 * m + t1[r - 5];
    };

    for (int idx = tid; idx < n * n; idx += NTHR) {
        int ri = idx / n, ci = idx % n;
        A[ri * LU_STRIDE + ci] = (double)wgt[chan(ri) * Cn + chan(ci)];
    }
    if (tid == 0) s_acc = 0.0;
    __syncthreads();

    for (int k = 0; k < n; k++) {
        double v = -1.0;
        int vi = tid;
        if (tid >= k && tid < n) v = fabs(A[tid * LU_STRIDE + k]);
        if (tid < 64) {
#pragma unroll
            for (int off = 16; off; off >>= 1) {
                double ov = __shfl_down_sync(0xffffffffu, v, off);
                int    oi = __shfl_down_sync(0xffffffffu, vi, off);
                if (ov > v) { v = ov; vi = oi; }
            }
            if ((tid & 31) == 0) { s_val[tid >> 5] = v; s_idx[tid >> 5] = vi; }
        }
        __syncthreads();
        if (tid == 0) {
            double bv = s_val[0]; int bi = s_idx[0];
            if (n > 32 && s_val[1] > bv) { bv = s_val[1]; bi = s_idx[1]; }
            s_piv = bi;
            s_acc += log(bv);
        }
        __syncthreads();
        const int piv = s_piv;
        if (piv != k && tid < n) {
            double t = A[k * LU_STRIDE + tid];
            A[k * LU_STRIDE + tid]   = A[piv * LU_STRIDE + tid];
            A[piv * LU_STRIDE + tid] = t;
        }
        __syncthreads();
        if (tid > k && tid < n) {
            double m = A[tid * LU_STRIDE + k] / A[k * LU_STRIDE + k];
            for (int c = k + 1; c < n; c++)
                A[tid * LU_STRIDE + c] -= m * A[k * LU_STRIDE + c];
        }
        __syncthreads();
    }

    if (tid == 0) {
        g_dlog[r] = s_acc * pixw;
        __threadfence();
        s_ticket = atomicAdd(&g_count, 1);
    }
    __syncthreads();
    if (s_ticket == NLOG - 1) {
        __threadfence();
        if (tid < Bn) {
            volatile double* gd = g_dlog;
            double s = 0.0;
#pragma unroll
            for (int k = 0; k < NLOG; k++) s += gd[k];
            outld[tid] = ldin[tid] + (float)s;
        }
        if (tid == 0) g_count = 0;
    }
}

// ---- main: persistent conv blocks; bf16-split mma.sync GEMM per 64-pixel tile ----
extern "C" __global__ void __launch_bounds__(NTHR)
ic1x1_kernel(const float* __restrict__ x, const float* __restrict__ wgt,
             const float* __restrict__ ldin,
             float* __restrict__ out, float* __restrict__ outld)
{
    extern __shared__ __align__(16) unsigned char smem_raw[];

    const int bx  = blockIdx.x;
    const int tid = threadIdx.x;
    if (bx < NLOG) { logdet_block(bx, wgt, ldin, outld, smem_raw); return; }

    __nv_bfloat16* wh = reinterpret_cast<__nv_bfloat16*>(smem_raw);
    __nv_bfloat16* wl = wh + 64 * AST;
    __nv_bfloat16* ah = wl + 64 * AST;
    __nv_bfloat16* al = ah + 64 * AST;
    const uint32_t* wh32 = reinterpret_cast<const uint32_t*>(wh);
    const uint32_t* wl32 = reinterpret_cast<const uint32_t*>(wl);
    const uint32_t* ah32 = reinterpret_cast<const uint32_t*>(ah);
    const uint32_t* al32 = reinterpret_cast<const uint32_t*>(al);

    // ---- W -> bf16 hi/lo, once per persistent block.  wh[co][ci], stride 72 ----
#pragma unroll
    for (int it = 0; it < 16; it++) {
        int idx = tid + it * NTHR;          // pair index 0..2047
        int co  = idx >> 5;
        int cp  = idx & 31;                 // ci pair
        float2 wv = *reinterpret_cast<const float2*>(wgt + co * 64 + cp * 2);
        float h0 = __bfloat162float(__float2bfloat16_rn(wv.x));
        float h1 = __bfloat162float(__float2bfloat16_rn(wv.y));
        int e = co * AST + cp * 2;          // even
        *reinterpret_cast<uint32_t*>(&wh[e]) = pack_bf16x2(h1, h0);
        *reinterpret_cast<uint32_t*>(&wl[e]) = pack_bf16x2(wv.y - h1, wv.x - h0);
    }

    const int lane = tid & 31;
    const int w16  = (tid >> 5) * 16;       // warp's m-offset
    const int frow = lane >> 2;             // t/4
    const int fkq  = (lane & 3) << 1;       // 2*(t%4)

    for (int t = bx - NLOG; t < NT_TILES; t += NCONV) {
        const int jt = t % JT;
        const int i  = (t / JT) % HP;       // shifted row 0..160
        const int bb = t / (JT * HP);
        const int j0 = jt * 64;
        const float* xb = x + (size_t)bb * (Cn * Hn * Wn);

        // ---- gather 64 pixels x 64 ci -> bf16 hi/lo (2 threads per pixel) ----
        {
            const int pix = tid >> 1;
            const int jj  = j0 + pix;       // shifted col (may exceed 160 -> zeros)
#pragma unroll
            for (int n = 0; n < 16; n++) {
                int cg2 = ((tid & 1) << 4) + n;
                int p  = cg2 & 1;
                int pp = 1 - p;
                int gb = (cg2 >> 1) * 4;
                int sc0 = gb | (pp << 1) | 1;    // ci even: sj = jj-1
                int sc1 = gb | (pp << 1);        // ci odd : sj = jj
                int si  = i - pp;
                float v0 = 0.0f, v1 = 0.0f;
                if ((unsigned)si < (unsigned)Hn) {
                    if ((unsigned)(jj - 1) < (unsigned)Wn) v0 = xb[(sc0 * Hn + si) * Wn + (jj - 1)];
                    if (jj < Wn)                            v1 = xb[(sc1 * Hn + si) * Wn + jj];
                }
                float h0 = __bfloat162float(__float2bfloat16_rn(v0));
                float h1 = __bfloat162float(__float2bfloat16_rn(v1));
                int e = pix * AST + cg2 * 2;
                *reinterpret_cast<uint32_t*>(&ah[e]) = pack_bf16x2(h1, h0);
                *reinterpret_cast<uint32_t*>(&al[e]) = pack_bf16x2(v1 - h1, v0 - h0);
            }
        }
        __syncthreads();

        // ---- warp GEMM: m16 x n64 x k64, split bf16 (hh + hl + lh) ----
        float d[8][4];
#pragma unroll
        for (int nt = 0; nt < 8; nt++)
#pragma unroll
            for (int r = 0; r < 4; r++) d[nt][r] = 0.0f;

#pragma unroll
        for (int kt = 0; kt < 4; kt++) {
            const int k0 = kt * 16 + fkq;
            uint32_t a_h[4], a_l[4];
            a_h[0] = ah32[((w16 + frow)     * AST + k0)     >> 1];
            a_h[1] = ah32[((w16 + frow + 8) * AST + k0)     >> 1];
            a_h[2] = ah32[((w16 + frow)     * AST + k0 + 8) >> 1];
            a_h[3] = ah32[((w16 + frow + 8) * AST + k0 + 8) >> 1];
            a_l[0] = al32[((w16 + frow)     * AST + k0)     >> 1];
            a_l[1] = al32[((w16 + frow + 8) * AST + k0)     >> 1];
            a_l[2] = al32[((w16 + frow)     * AST + k0 + 8) >> 1];
            a_l[3] = al32[((w16 + frow + 8) * AST + k0 + 8) >> 1];
#pragma unroll
            for (int nt = 0; nt < 8; nt++) {
                const int nrow = nt * 8 + frow;
                uint32_t b_h0 = wh32[(nrow * AST + k0)     >> 1];
                uint32_t b_h1 = wh32[(nrow * AST + k0 + 8) >> 1];
                uint32_t b_l0 = wl32[(nrow * AST + k0)     >> 1];
                uint32_t b_l1 = wl32[(nrow * AST + k0 + 8) >> 1];
                mma_bf16(d[nt], a_h, b_h0, b_h1);
                mma_bf16(d[nt], a_h, b_l0, b_l1);
                mma_bf16(d[nt], a_l, b_h0, b_h1);
            }
        }

        // ---- scatter through inverse shift (sector-aligned: 8 consecutive j per reg) ----
        float* ob = out + (size_t)bb * (Cn * Hn * Wn);
#pragma unroll
        for (int nt = 0; nt < 8; nt++) {
#pragma unroll
            for (int r = 0; r < 4; r++) {
                int c = nt * 8 + fkq + (r & 1);
                int m = w16 + frow + ((r & 2) << 2);
                int j = j0 + m;
                int P = (c >> 1) & 1, Q = c & 1;
                int dc = (c & ~3) | ((1 - P) << 1) | (1 - Q);
                int di = i - (1 - P);
                int dj = j - (1 - Q);
                if ((unsigned)di < (unsigned)Hn && (unsigned)dj < (unsigned)Wn)
                    ob[(dc * Hn + di) * Wn + dj] = d[nt][r];
            }
        }
        __syncthreads();
    }
}

extern "C" void kernel_launch(void* const* d_in, const int* in_sizes, int n_in,
                              void* d_out, int out_size)
{
    const float *x = nullptr, *ld = nullptr, *w = nullptr;
    for (int k = 0; k < n_in; k++) {
        if (in_sizes[k] == Cn * Cn)      w  = (const float*)d_in[k];
        else if (in_sizes[k] == Bn)      ld = (const float*)d_in[k];
        else                             x  = (const float*)d_in[k];
    }
    float* out   = (float*)d_out;
    float* outld = out + (out_size - Bn);

    ic1x1_kernel<<<NLOG + NCONV, NTHR, SMEM_BYTES>>>(x, w, ld, out, outld);
}

// round 7
// speedup vs baseline: 4.7984x; 1.6523x over previous
#include <cuda_runtime.h>
#include <cuda_bf16.h>
#include <cstdint>

#define Bn 16
#define Cn 64
#define Hn 160
#define Wn 160
#define HP 161
#define NLOG 9
#define NPIX (Bn * HP * HP)        // 414736 = 16 * 25921
#define NTILES (NPIX / 16)         // 25921 full 16-pixel warp tiles
#define NCONV 888                  // 148 * 6 persistent conv blocks
#define NTHR 128
#define NWARPS (NCONV * 4)
#define AST 72                     // bf16 element stride of W smem rows
#define LU_STRIDE 65
#define SMEM_BYTES (2 * 64 * AST * 2)   // Wh+Wl = 18432 ; fp32 LU needs 16640 (fits)

__device__ double g_dlog[NLOG];
__device__ int    g_count = 0;

__device__ __forceinline__ void mma_bf16(float* d, const uint32_t* a, uint32_t b0, uint32_t b1) {
    asm volatile(
        "mma.sync.aligned.m16n8k16.row.col.f32.bf16.bf16.f32 "
        "{%0,%1,%2,%3}, {%4,%5,%6,%7}, {%8,%9}, {%0,%1,%2,%3};"
        : "+f"(d[0]), "+f"(d[1]), "+f"(d[2]), "+f"(d[3])
        : "r"(a[0]), "r"(a[1]), "r"(a[2]), "r"(a[3]), "r"(b0), "r"(b1));
}
__device__ __forceinline__ uint32_t pack_bf16x2(float hi, float lo) {
    uint32_t r;
    asm("cvt.rn.bf16x2.f32 %0, %1, %2;" : "=r"(r) : "f"(hi), "f"(lo));
    return r;
}

// ---- blocks 0..8: one fp32 LU each (log accumulated in fp64); last finisher writes logdet ----
__device__ void logdet_block(int r, const float* __restrict__ wgt,
                             const float* __restrict__ ldin,
                             float* __restrict__ outld,
                             unsigned char* smem_raw)
{
    float* A = reinterpret_cast<float*>(smem_raw);
    __shared__ float  s_val[2];
    __shared__ int    s_idx[2];
    __shared__ int    s_piv;
    __shared__ double s_acc;
    __shared__ int    s_ticket;

    const int tid = threadIdx.x;
    const int n   = (r == 0) ? 64 : (r <= 4 ? 32 : 16);
    const double pixw = (r == 0) ? (double)(Hn - 1) * (double)(Wn - 1)
                                 : (r <= 4 ? (double)(Wn - 1) : 1.0);
    auto chan = [&](int m) -> int {
        if (r == 0) return m;
        if (r <= 4) {
            const int t2[4][2] = {{2, 3}, {0, 1}, {1, 3}, {0, 2}};
            return 4 * (m >> 1) + t2[r - 1][m & 1];
        }
        const int t1[4] = {3, 2, 1, 0};
        return 4 * m + t1[r - 5];
    };

    for (int idx = tid; idx < n * n; idx += NTHR) {
        int ri = idx / n, ci = idx % n;
        A[ri * LU_STRIDE + ci] = wgt[chan(ri) * Cn + chan(ci)];
    }
    if (tid == 0) s_acc = 0.0;
    __syncthreads();

    for (int k = 0; k < n; k++) {
        float v = -1.0f;
        int vi = tid;
        if (tid >= k && tid < n) v = fabsf(A[tid * LU_STRIDE + k]);
        if (tid < 64) {
#pragma unroll
            for (int off = 16; off; off >>= 1) {
                float ov = __shfl_down_sync(0xffffffffu, v, off);
                int   oi = __shfl_down_sync(0xffffffffu, vi, off);
                if (ov > v) { v = ov; vi = oi; }
            }
            if ((tid & 31) == 0) { s_val[tid >> 5] = v; s_idx[tid >> 5] = vi; }
        }
        __syncthreads();
        if (tid == 0) {
            float bv = s_val[0]; int bi = s_idx[0];
            if (n > 32 && s_val[1] > bv) { bv = s_val[1]; bi = s_idx[1]; }
            s_piv = bi;
            s_acc += log((double)bv);
        }
        __syncthreads();
        const int piv = s_piv;
        if (piv != k && tid < n) {
            float t = A[k * LU_STRIDE + tid];
            A[k * LU_STRIDE + tid]   = A[piv * LU_STRIDE + tid];
            A[piv * LU_STRIDE + tid] = t;
        }
        __syncthreads();
        if (tid > k && tid < n) {
            float m = A[tid * LU_STRIDE + k] / A[k * LU_STRIDE + k];
            for (int c = k + 1; c < n; c++)
                A[tid * LU_STRIDE + c] -= m * A[k * LU_STRIDE + c];
        }
        __syncthreads();
    }

    if (tid == 0) {
        g_dlog[r] = s_acc * pixw;
        __threadfence();
        s_ticket = atomicAdd(&g_count, 1);
    }
    __syncthreads();
    if (s_ticket == NLOG - 1) {
        __threadfence();
        if (tid < Bn) {
            volatile double* gd = g_dlog;
            double s = 0.0;
#pragma unroll
            for (int k = 0; k < NLOG; k++) s += gd[k];
            outld[tid] = ldin[tid] + (float)s;
        }
        if (tid == 0) g_count = 0;
    }
}

// ---- main: warp-autonomous 16-pixel tiles, fragment-direct gather, bf16-split mma ----
extern "C" __global__ void __launch_bounds__(NTHR)
ic1x1_kernel(const float* __restrict__ x, const float* __restrict__ wgt,
             const float* __restrict__ ldin,
             float* __restrict__ out, float* __restrict__ outld)
{
    extern __shared__ __align__(16) unsigned char smem_raw[];

    const int bx  = blockIdx.x;
    const int tid = threadIdx.x;
    if (bx < NLOG) { logdet_block(bx, wgt, ldin, outld, smem_raw); return; }

    __nv_bfloat16* wh = reinterpret_cast<__nv_bfloat16*>(smem_raw);
    __nv_bfloat16* wl = wh + 64 * AST;
    const uint32_t* wh32 = reinterpret_cast<const uint32_t*>(wh);
    const uint32_t* wl32 = reinterpret_cast<const uint32_t*>(wl);

    // ---- W -> bf16 hi/lo once per block.  wh[co][ci], element stride 72 ----
#pragma unroll
    for (int it = 0; it < 16; it++) {
        int idx = tid + it * NTHR;           // pair index 0..2047
        int co  = idx >> 5;
        int cp  = idx & 31;
        float2 wv = *reinterpret_cast<const float2*>(wgt + co * 64 + cp * 2);
        float h0 = __bfloat162float(__float2bfloat16_rn(wv.x));
        float h1 = __bfloat162float(__float2bfloat16_rn(wv.y));
        int e = co * AST + cp * 2;
        *reinterpret_cast<uint32_t*>(&wh[e]) = pack_bf16x2(h1, h0);
        *reinterpret_cast<uint32_t*>(&wl[e]) = pack_bf16x2(wv.y - h1, wv.x - h0);
    }
    __syncthreads();

    const int lane = tid & 31;
    const int frow = lane >> 2;      // 0..7
    const int q2   = lane & 3;       // cg2 low bits
    const int fkq  = q2 << 1;

    const int wg = (bx - NLOG) * 4 + (tid >> 5);

    for (int t = wg; t < NTILES; t += NWARPS) {
        // ---- decode this thread's two pixels ----
        const int pidA = t * 16 + frow;
        const int pidB = pidA + 8;
        int bbA = pidA / (HP * HP); int rA = pidA - bbA * HP * HP;
        int iiA = rA / HP;          int jjA = rA - iiA * HP;
        int bbB = pidB / (HP * HP); int rB = pidB - bbB * HP * HP;
        int iiB = rB / HP;          int jjB = rB - iiB * HP;
        const float* xbA = x + (size_t)bbA * (Cn * Hn * Wn);
        const float* xbB = x + (size_t)bbB * (Cn * Hn * Wn);

        // ---- fragment-direct gather: 8 bf16x2 pairs per pixel, straight to regs ----
        uint32_t ahA[8], alA[8], ahB[8], alB[8];
#pragma unroll
        for (int h = 0; h < 8; h++) {
            const int cg2 = q2 + 4 * h;
            const int p   = cg2 & 1;
            const int pp  = 1 - p;
            const int gb  = (cg2 >> 1) * 4;
            const int sc0 = gb + (pp << 1) + 1;   // even ci -> col j-1
            const int sc1 = gb + (pp << 1);       // odd  ci -> col j
            {
                const int si = iiA - pp;
                const bool rok = (unsigned)si < (unsigned)Hn;
                float v0 = (rok && (unsigned)(jjA - 1) < (unsigned)Wn)
                             ? xbA[(sc0 * Hn + si) * Wn + jjA - 1] : 0.0f;
                float v1 = (rok && jjA < Wn)
                             ? xbA[(sc1 * Hn + si) * Wn + jjA] : 0.0f;
                float h0 = __bfloat162float(__float2bfloat16_rn(v0));
                float h1 = __bfloat162float(__float2bfloat16_rn(v1));
                ahA[h] = pack_bf16x2(h1, h0);
                alA[h] = pack_bf16x2(v1 - h1, v0 - h0);
            }
            {
                const int si = iiB - pp;
                const bool rok = (unsigned)si < (unsigned)Hn;
                float v0 = (rok && (unsigned)(jjB - 1) < (unsigned)Wn)
                             ? xbB[(sc0 * Hn + si) * Wn + jjB - 1] : 0.0f;
                float v1 = (rok && jjB < Wn)
                             ? xbB[(sc1 * Hn + si) * Wn + jjB] : 0.0f;
                float h0 = __bfloat162float(__float2bfloat16_rn(v0));
                float h1 = __bfloat162float(__float2bfloat16_rn(v1));
                ahB[h] = pack_bf16x2(h1, h0);
                alB[h] = pack_bf16x2(v1 - h1, v0 - h0);
            }
        }

        // ---- warp GEMM m16 x n64 x k64, split bf16 (hh + hl + lh) ----
        float d[8][4];
#pragma unroll
        for (int nt = 0; nt < 8; nt++)
#pragma unroll
            for (int r = 0; r < 4; r++) d[nt][r] = 0.0f;

#pragma unroll
        for (int kt = 0; kt < 4; kt++) {
            const int k0 = kt * 16 + fkq;
            uint32_t A_h[4] = { ahA[2 * kt], ahB[2 * kt], ahA[2 * kt + 1], ahB[2 * kt + 1] };
            uint32_t A_l[4] = { alA[2 * kt], alB[2 * kt], alA[2 * kt + 1], alB[2 * kt + 1] };
#pragma unroll
            for (int nt = 0; nt < 8; nt++) {
                const int nrow = nt * 8 + frow;
                uint32_t b_h0 = wh32[(nrow * AST + k0)     >> 1];
                uint32_t b_h1 = wh32[(nrow * AST + k0 + 8) >> 1];
                uint32_t b_l0 = wl32[(nrow * AST + k0)     >> 1];
                uint32_t b_l1 = wl32[(nrow * AST + k0 + 8) >> 1];
                mma_bf16(d[nt], A_h, b_h0, b_h1);
                mma_bf16(d[nt], A_h, b_l0, b_l1);
                mma_bf16(d[nt], A_l, b_h0, b_h1);
            }
        }

        // ---- scatter through inverse shift (predication == region masks) ----
        float* obA = out + (size_t)bbA * (Cn * Hn * Wn);
        float* obB = out + (size_t)bbB * (Cn * Hn * Wn);
#pragma unroll
        for (int nt = 0; nt < 8; nt++) {
#pragma unroll
            for (int r = 0; r < 4; r++) {
                const int c = nt * 8 + fkq + (r & 1);
                const int P = (c >> 1) & 1, Q = c & 1;
                const int dc = (c & ~3) | ((1 - P) << 1) | (1 - Q);
                const int ii = (r & 2) ? iiB : iiA;
                const int jj = (r & 2) ? jjB : jjA;
                float* ob    = (r & 2) ? obB : obA;
                const int di = ii - (1 - P);
                const int dj = jj - (1 - Q);
                if ((unsigned)di < (unsigned)Hn && (unsigned)dj < (unsigned)Wn)
                    ob[(dc * Hn + di) * Wn + dj] = d[nt][r];
            }
        }
    }
}

extern "C" void kernel_launch(void* const* d_in, const int* in_sizes, int n_in,
                              void* d_out, int out_size)
{
    const float *x = nullptr, *ld = nullptr, *w = nullptr;
    for (int k = 0; k < n_in; k++) {
        if (in_sizes[k] == Cn * Cn)      w  = (const float*)d_in[k];
        else if (in_sizes[k] == Bn)      ld = (const float*)d_in[k];
        else                             x  = (const float*)d_in[k];
    }
    float* out   = (float*)d_out;
    float* outld = out + (out_size - Bn);

    ic1x1_kernel<<<NLOG + NCONV, NTHR, SMEM_BYTES>>>(x, w, ld, out, outld);
}